// round 15
// baseline (speedup 1.0000x reference)
#include <cuda_runtime.h>
#include <cuda_fp16.h>
#include <cstdint>

#define BB 2
#define TT 2048
#define HH 1024
#define NHH 16
#define HSS 64

// ---------------- scratch (device globals; no allocation allowed) ----------
__device__ __half g_Qh [BB*NHH*TT*HSS];     // [bh][t][d-perm]
__device__ __half g_Kh [BB*NHH*TT*HSS];     // [bh][t][d-perm]
__device__ __half g_Vth[BB*NHH*HSS*TT];     // [bh][d][t-perm]  (transposed)
__device__ __half g_Yh [BB*TT*HH];          // [b][t][h-perm]
__device__ __half g_Xh [BB*TT*HH];          // k-perm fp16 x
__device__ __half g_Wqh[HH*HH];
__device__ __half g_Wkh[HH*HH];
__device__ __half g_Wvh[HH*HH];
__device__ __half g_Woh[HH*HH];

// ---------------------------------------------------------------------------
// helpers
// ---------------------------------------------------------------------------
__device__ __forceinline__ uint32_t f22h2(float lo, float hi) {
    __half2 h = __float22half2_rn(make_float2(lo, hi));
    return *reinterpret_cast<uint32_t*>(&h);
}

__device__ __forceinline__ void mma_f16(float c[4], const uint32_t a[4],
                                        const uint32_t b[2]) {
    asm volatile(
        "mma.sync.aligned.m16n8k16.row.col.f32.f16.f16.f32 "
        "{%0,%1,%2,%3}, {%4,%5,%6,%7}, {%8,%9}, {%0,%1,%2,%3};\n"
        : "+f"(c[0]), "+f"(c[1]), "+f"(c[2]), "+f"(c[3])
        : "r"(a[0]), "r"(a[1]), "r"(a[2]), "r"(a[3]),
          "r"(b[0]), "r"(b[1]));
}

#define CPA16(dst_u32, src_ptr) \
    asm volatile("cp.async.cg.shared.global [%0], [%1], 16;" \
                 :: "r"(dst_u32), "l"(src_ptr))
#define CPA_COMMIT()  asm volatile("cp.async.commit_group;")
#define CPA_WAITG(n)  asm volatile("cp.async.wait_group %0;" :: "n"(n))

// ---------------------------------------------------------------------------
// cvt: fp32 -> fp16 with per-16-element k-interleave permutation (R10).
// ---------------------------------------------------------------------------
__global__ void cvt_kernel(const float* __restrict__ x,
                           const float* __restrict__ Wq,
                           const float* __restrict__ Wk,
                           const float* __restrict__ Wv,
                           const float* __restrict__ Wo,
                           __half* __restrict__ Xh,
                           __half* __restrict__ Wqh, __half* __restrict__ Wkh,
                           __half* __restrict__ Wvh, __half* __restrict__ Woh)
{
    const int NX = (BB*TT*HH)/16;   // 262144 groups
    const int NW = (HH*HH)/16;      // 65536 per weight
    const int total = NX + 4*NW;
    for (int idx = blockIdx.x*blockDim.x + threadIdx.x; idx < total;
         idx += gridDim.x*blockDim.x) {
        const float4* s; uint4* d; int g;
        if (idx < NX) { s = (const float4*)x; d = (uint4*)Xh; g = idx; }
        else {
            int i = idx - NX, sel = i >> 16; g = i & 65535;
            s = (sel==0) ? (const float4*)Wq : (sel==1) ? (const float4*)Wk
              : (sel==2) ? (const float4*)Wv : (const float4*)Wo;
            d = (sel==0) ? (uint4*)Wqh : (sel==1) ? (uint4*)Wkh
              : (sel==2) ? (uint4*)Wvh : (uint4*)Woh;
        }
        float4 A = s[g*4+0], B = s[g*4+1], C = s[g*4+2], D = s[g*4+3];
        uint4 o0 = make_uint4(f22h2(A.x,A.y), f22h2(C.x,C.y),
                              f22h2(A.z,A.w), f22h2(C.z,C.w));
        uint4 o1 = make_uint4(f22h2(B.x,B.y), f22h2(D.x,D.y),
                              f22h2(B.z,B.w), f22h2(D.z,D.w));
        d[g*2+0] = o0;
        d[g*2+1] = o1;
    }
}

// ---------------------------------------------------------------------------
// fp16 GEMM body (exact R10 config): block 128x128x32, 256 thr, 8 warps 64x32.
// ---------------------------------------------------------------------------
struct GemmAcc { float c[4][4][4]; };

#define GSTR 24
#define GTILE (128*GSTR)

__device__ __forceinline__ void gemm_body_f16(const __half* __restrict__ A,
                                              const __half* __restrict__ W,
                                              uint32_t* dsm,
                                              int m0, int n0, GemmAcc& G)
{
    const int tid  = threadIdx.x;
    const int lane = tid & 31;
    const int w    = tid >> 5;
    const int g    = lane >> 2;
    const int t4   = lane & 3;
    const int wm   = w >> 2;
    const int wn   = w & 3;
    const uint32_t smaddr = (uint32_t)__cvta_generic_to_shared(dsm);

    #pragma unroll
    for (int im = 0; im < 4; im++)
        #pragma unroll
        for (int in = 0; in < 4; in++)
            #pragma unroll
            for (int q = 0; q < 4; q++) G.c[im][in][q] = 0.f;

    auto issue = [&](int tile, int st) {
        const int kt = tile * 32;                    // halves
        const uint32_t ab = smaddr + st*GTILE*4;
        const uint32_t bb = smaddr + (2*GTILE + st*GTILE)*4;
        #pragma unroll
        for (int l = 0; l < 2; l++) {
            int e = l*256 + tid, r = e >> 2, c = e & 3;
            CPA16(ab + (r*GSTR + c*4)*4, A + (size_t)(m0 + r)*1024 + kt + c*8);
            CPA16(bb + (r*GSTR + c*4)*4, W + (size_t)(n0 + r)*1024 + kt + c*8);
        }
        CPA_COMMIT();
    };

    issue(0, 0);

    for (int i = 0; i < 32; i++) {
        CPA_WAITG(0);
        __syncthreads();
        if (i + 1 < 32) issue(i + 1, (i + 1) & 1);

        const uint32_t* As = dsm + (i & 1)*GTILE;
        const uint32_t* Bs = dsm + 2*GTILE + (i & 1)*GTILE;
        #pragma unroll
        for (int ks = 0; ks < 2; ks++) {
            const int base = ks*8 + 2*t4;
            uint32_t af[4][4], bf[4][2];
            #pragma unroll
            for (int im = 0; im < 4; im++) {
                int r0 = wm*64 + im*16 + g;
                uint2 lo = *(const uint2*)&As[r0*GSTR + base];
                uint2 hi = *(const uint2*)&As[(r0+8)*GSTR + base];
                af[im][0] = lo.x; af[im][1] = hi.x;
                af[im][2] = lo.y; af[im][3] = hi.y;
            }
            #pragma unroll
            for (int in = 0; in < 4; in++) {
                int n = wn*32 + in*8 + g;
                uint2 y = *(const uint2*)&Bs[n*GSTR + base];
                bf[in][0] = y.x; bf[in][1] = y.y;
            }
            #pragma unroll
            for (int im = 0; im < 4; im++)
                #pragma unroll
                for (int in = 0; in < 4; in++)
                    mma_f16(G.c[im][in], af[im], bf[in]);
        }
    }
}

// ---------------------------------------------------------------------------
// Fused QKV projection (R10). grid (8, 32, 3): z selects {Q, K, V}.
// ---------------------------------------------------------------------------
__global__ __launch_bounds__(256, 2)
void gemm_qkv(const __half* __restrict__ Xh,
              const __half* __restrict__ Wqh, const __half* __restrict__ Wkh,
              const __half* __restrict__ Wvh,
              const float* __restrict__ bq, const float* __restrict__ bk,
              const float* __restrict__ bv,
              const float* __restrict__ rope,
              __half* __restrict__ Qh, __half* __restrict__ Kh,
              __half* __restrict__ Vth)
{
    extern __shared__ uint32_t dsm[];

    const int z = blockIdx.z;
    const __half* W   = (z == 0) ? Wqh : (z == 1) ? Wkh : Wvh;
    const float* bias = (z == 0) ? bq  : (z == 1) ? bk  : bv;

    const int m0 = blockIdx.y * 128;
    const int n0 = blockIdx.x * 128;

    GemmAcc G;
    gemm_body_f16(Xh, W, dsm, m0, n0, G);

    const int lane = threadIdx.x & 31;
    const int w    = threadIdx.x >> 5;
    const int g    = lane >> 2;
    const int t4   = lane & 3;
    const int wm   = w >> 2;
    const int wn   = w & 3;

    #pragma unroll
    for (int im = 0; im < 4; im++) {
        #pragma unroll
        for (int rh = 0; rh < 2; rh++) {
            int m  = m0 + wm*64 + im*16 + g + rh*8;
            int b  = m >> 11;
            int tt = m & 2047;
            #pragma unroll
            for (int in = 0; in < 4; in++) {
                int n = n0 + wn*32 + in*8 + 2*t4;
                float v0 = G.c[im][in][rh*2 + 0] + bias[n];
                float v1 = G.c[im][in][rh*2 + 1] + bias[n+1];
                int h = n >> 6, d = n & 63;
                if (z < 2) {
                    int i0 = d >> 1;
                    float cs = rope[((size_t)tt*32 + i0)*2 + 0];
                    float sn = rope[((size_t)tt*32 + i0)*2 + 1];
                    float nv0 = cs*v0 - sn*v1;
                    float nv1 = sn*v0 + cs*v1;
                    int wd = d >> 1, blk = wd >> 3, ib = wd & 7;
                    int wp = blk*8 + ((ib < 4) ? 2*ib : 2*(ib-4) + 1);
                    uint32_t* oh = (uint32_t*)((z == 0) ? Qh : Kh);
                    oh[((size_t)(b*NHH + h)*TT + tt)*32 + wp] = f22h2(nv0, nv1);
                } else {
                    int tl = tt & 15;
                    int tlp = 2*tl - (tl & 1) - ((tl >> 3)*14);
                    size_t base = (size_t)(b*NHH + h)*64;
                    size_t tcol = (size_t)(tt & ~15) + tlp;
                    Vth[(base + d    )*TT + tcol] = __float2half_rn(v0);
                    Vth[(base + d + 1)*TT + tcol] = __float2half_rn(v1);
                }
            }
        }
    }
}

// ---------------------------------------------------------------------------
// Output projection (R10): out[m,n] = Yh @ Woh^T (fp32 result).
// ---------------------------------------------------------------------------
__global__ __launch_bounds__(256, 2)
void gemm_out(const __half* __restrict__ Yh, const __half* __restrict__ Woh,
              float* __restrict__ out)
{
    extern __shared__ uint32_t dsm[];

    const int m0 = blockIdx.y * 128;
    const int n0 = blockIdx.x * 128;

    GemmAcc G;
    gemm_body_f16(Yh, Woh, dsm, m0, n0, G);

    const int lane = threadIdx.x & 31;
    const int w    = threadIdx.x >> 5;
    const int g    = lane >> 2;
    const int t4   = lane & 3;
    const int wm   = w >> 2;
    const int wn   = w & 3;

    #pragma unroll
    for (int im = 0; im < 4; im++) {
        #pragma unroll
        for (int rh = 0; rh < 2; rh++) {
            int m = m0 + wm*64 + im*16 + g + rh*8;
            #pragma unroll
            for (int in = 0; in < 4; in++) {
                int n = n0 + wn*32 + in*8 + 2*t4;
                *(float2*)(out + (size_t)m*1024 + n) =
                    make_float2(G.c[im][in][rh*2 + 0], G.c[im][in][rh*2 + 1]);
            }
        }
    }
}

// ---------------------------------------------------------------------------
// fp16 MMA flash attention — q-tile 128, 256 threads (8 warps x 16 rows).
// K/V tiles of 64 keys, double-buffered cp.async. Warp math identical to R10.
// Fully-future tiles inside the loop are correct: scores -1e10 -> weight 0
// for normal rows, weight 1 for degenerate rows (reference semantics).
// ---------------------------------------------------------------------------
#define KSTR 40
#define VSTR 40
#define ABUF (64*KSTR + 64*VSTR + 64)
#define QSTR 32

__global__ __launch_bounds__(256)
void attn_mma(const __half* __restrict__ Q,
              const __half* __restrict__ K,
              const __half* __restrict__ Vt,
              const int* __restrict__ masks,
              __half* __restrict__ Y)
{
    extern __shared__ uint32_t sm[];
    __shared__ int s_any;

    const int tid  = threadIdx.x;
    const int w    = tid >> 5;          // 0..7
    const int lane = tid & 31;
    const int g    = lane >> 2;
    const int t4   = lane & 3;
    const int bh   = blockIdx.y;
    const int b    = bh >> 4;
    const int h    = bh & 15;
    const int qt   = gridDim.x - 1 - blockIdx.x;   // heavy blocks first
    const int q0   = qt * 128;
    const __half* Qb  = Q  + (size_t)bh*TT*HSS;
    const __half* Kb  = K  + (size_t)bh*TT*HSS;
    const __half* Vtb = Vt + (size_t)bh*HSS*TT;
    const int*    mb  = masks + b*TT;
    const uint32_t smaddr = (uint32_t)__cvta_generic_to_shared(sm);

    const int qr0 = q0 + w*16 + g;
    const int qr1 = qr0 + 8;

    // stage Q tile (128 rows x 32 words, stride 32) then lift fragments
    #pragma unroll
    for (int l = 0; l < 4; l++) {
        int e = l*256 + tid, r = e >> 3, c = e & 7;
        *(uint4*)&sm[r*QSTR + c*4] =
            *(const uint4*)(Qb + (size_t)(q0 + r)*HSS + c*8);
    }
    __syncthreads();
    uint32_t qf[4][4];
    {
        const int qrow0 = (w*16 + g)*QSTR;
        const int qrow1 = (w*16 + g + 8)*QSTR;
        #pragma unroll
        for (int ks = 0; ks < 4; ks++) {
            uint2 lo = *(const uint2*)&sm[qrow0 + ks*8 + 2*t4];
            uint2 hi = *(const uint2*)&sm[qrow1 + ks*8 + 2*t4];
            qf[ks][0] = lo.x; qf[ks][1] = hi.x;
            qf[ks][2] = lo.y; qf[ks][3] = hi.y;
        }
    }
    __syncthreads();

    auto issue = [&](int j, int s) {
        const int kbase = j*64;
        const uint32_t base = smaddr + s*ABUF*4;
        #pragma unroll
        for (int l = 0; l < 2; l++) {
            int e = l*256 + tid, r = e >> 3, c = e & 7;
            CPA16(base + (r*KSTR + c*4)*4,
                  Kb + (size_t)(kbase + r)*HSS + c*8);
            CPA16(base + (64*KSTR + r*VSTR + c*4)*4,
                  Vtb + (size_t)r*TT + kbase + c*8);
        }
        if (tid < 16)
            CPA16(base + (64*KSTR + 64*VSTR)*4 + tid*16, mb + kbase + tid*4);
        CPA_COMMIT();
    };

    float oc[8][4];
    #pragma unroll
    for (int n = 0; n < 8; n++)
        #pragma unroll
        for (int q = 0; q < 4; q++) oc[n][q] = 0.f;
    float mrun0 = -1e30f, mrun1 = -1e30f;
    float l0 = 0.f, l1 = 0.f;

    const int nkt = 2*qt + 2;           // k-tiles covering the 128 q-rows
    issue(0, 0);

    for (int j = 0; j < nkt; j++) {
        const int s = j & 1;
        __syncthreads();
        if (j + 1 < nkt) { issue(j + 1, s ^ 1); CPA_WAITG(1); }
        else             { CPA_WAITG(0); }
        __syncthreads();

        const uint32_t* Ks = sm + s*ABUF;
        const uint32_t* Vs = Ks + 64*KSTR;
        const int*      mi = (const int*)(Vs + 64*VSTR);
        const int kbase = j*64;

        // ---- S = Q K^T ----
        float sc[8][4];
        #pragma unroll
        for (int n = 0; n < 8; n++)
            #pragma unroll
            for (int q = 0; q < 4; q++) sc[n][q] = 0.f;
        #pragma unroll
        for (int ks = 0; ks < 4; ks++) {
            #pragma unroll
            for (int n = 0; n < 8; n++) {
                uint2 y = *(const uint2*)&Ks[(n*8 + g)*KSTR + ks*8 + 2*t4];
                uint32_t bb[2] = {y.x, y.y};
                mma_f16(sc[n], qf[ks], bb);
            }
        }

        // ---- scale + masks (causal live on the last two tiles) ----
        const bool diag = (j >= nkt - 2);
        float mx0 = -1e30f, mx1 = -1e30f;
        #pragma unroll
        for (int n = 0; n < 8; n++) {
            bool m0i = mi[n*8 + 2*t4]     != 0;
            bool m1i = mi[n*8 + 2*t4 + 1] != 0;
            bool x00 = m0i, x01 = m1i, x10 = m0i, x11 = m1i;
            if (diag) {
                int c0 = kbase + n*8 + 2*t4;
                int c1 = c0 + 1;
                x00 |= (c0 > qr0); x01 |= (c1 > qr0);
                x10 |= (c0 > qr1); x11 |= (c1 > qr1);
            }
            float s00 = x00 ? -1e10f : sc[n][0]*0.125f;
            float s01 = x01 ? -1e10f : sc[n][1]*0.125f;
            float s10 = x10 ? -1e10f : sc[n][2]*0.125f;
            float s11 = x11 ? -1e10f : sc[n][3]*0.125f;
            sc[n][0] = s00; sc[n][1] = s01; sc[n][2] = s10; sc[n][3] = s11;
            mx0 = fmaxf(mx0, fmaxf(s00, s01));
            mx1 = fmaxf(mx1, fmaxf(s10, s11));
        }
        mx0 = fmaxf(mx0, __shfl_xor_sync(0xffffffffu, mx0, 1));
        mx0 = fmaxf(mx0, __shfl_xor_sync(0xffffffffu, mx0, 2));
        mx1 = fmaxf(mx1, __shfl_xor_sync(0xffffffffu, mx1, 1));
        mx1 = fmaxf(mx1, __shfl_xor_sync(0xffffffffu, mx1, 2));

        float mnew0 = fmaxf(mrun0, mx0);
        float mnew1 = fmaxf(mrun1, mx1);
        float corr0 = __expf(mrun0 - mnew0);
        float corr1 = __expf(mrun1 - mnew1);
        mrun0 = mnew0; mrun1 = mnew1;

        float ps0 = 0.f, ps1 = 0.f;
        #pragma unroll
        for (int n = 0; n < 8; n++) {
            float p00 = __expf(sc[n][0] - mnew0);
            float p01 = __expf(sc[n][1] - mnew0);
            float p10 = __expf(sc[n][2] - mnew1);
            float p11 = __expf(sc[n][3] - mnew1);
            ps0 += p00 + p01;
            ps1 += p10 + p11;
            sc[n][0] = p00; sc[n][1] = p01; sc[n][2] = p10; sc[n][3] = p11;
        }
        ps0 += __shfl_xor_sync(0xffffffffu, ps0, 1);
        ps0 += __shfl_xor_sync(0xffffffffu, ps0, 2);
        ps1 += __shfl_xor_sync(0xffffffffu, ps1, 1);
        ps1 += __shfl_xor_sync(0xffffffffu, ps1, 2);
        l0 = l0*corr0 + ps0;
        l1 = l1*corr1 + ps1;

        #pragma unroll
        for (int n = 0; n < 8; n++) {
            oc[n][0] *= corr0; oc[n][1] *= corr0;
            oc[n][2] *= corr1; oc[n][3] *= corr1;
        }

        // ---- O += P V ----
        #pragma unroll
        for (int c = 0; c < 4; c++) {
            uint32_t a[4];
            a[0] = f22h2(sc[2*c][0],   sc[2*c][1]);
            a[1] = f22h2(sc[2*c][2],   sc[2*c][3]);
            a[2] = f22h2(sc[2*c+1][0], sc[2*c+1][1]);
            a[3] = f22h2(sc[2*c+1][2], sc[2*c+1][3]);
            #pragma unroll
            for (int n = 0; n < 8; n++) {
                uint2 y = *(const uint2*)&Vs[(n*8 + g)*VSTR + c*8 + 2*t4];
                uint32_t bb[2] = {y.x, y.y};
                mma_f16(oc[n], a, bb);
            }
        }
    }

    // ---- degenerate rows: uniform weight over remaining future tiles ----
    bool dg0 = mrun0 < -9.0e9f;
    bool dg1 = mrun1 < -9.0e9f;
    if (tid == 0) s_any = 0;
    __syncthreads();
    if (dg0 || dg1) s_any = 1;
    __syncthreads();
    if (s_any) {
        uint32_t* Vs0 = sm + 64*KSTR;
        uint32_t one2 = f22h2(1.f, 1.f);
        uint32_t a[4];
        a[0] = dg0 ? one2 : 0u;
        a[1] = dg1 ? one2 : 0u;
        a[2] = a[0];
        a[3] = a[1];
        for (int j = nkt; j < TT/64; j++) {
            __syncthreads();
            #pragma unroll
            for (int l = 0; l < 2; l++) {
                int e = l*256 + tid, r = e >> 3, c = e & 7;
                *(uint4*)&Vs0[r*VSTR + c*4] =
                    *(const uint4*)(Vtb + (size_t)r*TT + j*64 + c*8);
            }
            __syncthreads();
            #pragma unroll
            for (int c = 0; c < 4; c++) {
                #pragma unroll
                for (int n = 0; n < 8; n++) {
                    uint2 y = *(const uint2*)&Vs0[(n*8 + g)*VSTR + c*8 + 2*t4];
                    uint32_t bb[2] = {y.x, y.y};
                    mma_f16(oc[n], a, bb);
                }
            }
        }
        float add = 64.f * (TT/64 - nkt);
        if (dg0) l0 += add;
        if (dg1) l1 += add;
    }

    // ---- normalize + store fp16 (feature-permuted for gemm_out) ----
    float inv0 = 1.f / l0;
    float inv1 = 1.f / l1;
    int t0 = q0 + w*16 + g;
    uint32_t* Yw = (uint32_t*)Y;
    size_t base0 = (size_t)(b*TT + t0    )*512 + h*32;
    size_t base1 = (size_t)(b*TT + t0 + 8)*512 + h*32;
    #pragma unroll
    for (int n = 0; n < 8; n++) {
        int wp = (n >> 1)*8 + 2*t4 + (n & 1);
        Yw[base0 + wp] = f22h2(oc[n][0]*inv0, oc[n][1]*inv0);
        Yw[base1 + wp] = f22h2(oc[n][2]*inv1, oc[n][3]*inv1);
    }
}

// ---------------------------------------------------------------------------
extern "C" void kernel_launch(void* const* d_in, const int* in_sizes, int n_in,
                              void* d_out, int out_size)
{
    const float* x     = (const float*)d_in[0];
    const int*   masks = (const int*)  d_in[1];
    const float* Wq    = (const float*)d_in[2];
    const float* bq    = (const float*)d_in[3];
    const float* Wk    = (const float*)d_in[4];
    const float* bk    = (const float*)d_in[5];
    const float* Wv    = (const float*)d_in[6];
    const float* bv    = (const float*)d_in[7];
    const float* Wo    = (const float*)d_in[8];
    const float* rope  = (const float*)d_in[9];
    float* out = (float*)d_out;

    __half *Qh, *Kh, *Vth, *Yh, *Xh, *Wqh, *Wkh, *Wvh, *Woh;
    cudaGetSymbolAddress((void**)&Qh,  g_Qh);
    cudaGetSymbolAddress((void**)&Kh,  g_Kh);
    cudaGetSymbolAddress((void**)&Vth, g_Vth);
    cudaGetSymbolAddress((void**)&Yh,  g_Yh);
    cudaGetSymbolAddress((void**)&Xh,  g_Xh);
    cudaGetSymbolAddress((void**)&Wqh, g_Wqh);
    cudaGetSymbolAddress((void**)&Wkh, g_Wkh);
    cudaGetSymbolAddress((void**)&Wvh, g_Wvh);
    cudaGetSymbolAddress((void**)&Woh, g_Woh);

    const int gemm_smem = 4*GTILE*(int)sizeof(uint32_t);   // 49152 B
    const int attn_smem = 2*ABUF*(int)sizeof(uint32_t);    // 41472 B
    cudaFuncSetAttribute(gemm_qkv,
                         cudaFuncAttributeMaxDynamicSharedMemorySize, gemm_smem);
    cudaFuncSetAttribute(gemm_out,
                         cudaFuncAttributeMaxDynamicSharedMemorySize, gemm_smem);
    cudaFuncSetAttribute(attn_mma,
                         cudaFuncAttributeMaxDynamicSharedMemorySize, attn_smem);

    cvt_kernel<<<2048, 256>>>(x, Wq, Wk, Wv, Wo, Xh, Wqh, Wkh, Wvh, Woh);

    gemm_qkv<<<dim3(8, 32, 3), 256, gemm_smem>>>(Xh, Wqh, Wkh, Wvh,
                                                 bq, bk, bv, rope,
                                                 Qh, Kh, Vth);

    attn_mma<<<dim3(TT/128, BB*NHH), 256, attn_smem>>>(Qh, Kh, Vth, masks, Yh);

    gemm_out<<<dim3(8, 32), 256, gemm_smem>>>(Yh, Woh, out);
}

// round 17
// speedup vs baseline: 1.1422x; 1.1422x over previous
#include <cuda_runtime.h>
#include <cuda_fp16.h>
#include <cstdint>

#define BB 2
#define TT 2048
#define HH 1024
#define NHH 16
#define HSS 64

// ---------------- scratch (device globals; no allocation allowed) ----------
__device__ __half g_Qh [BB*NHH*TT*HSS];     // [bh][t][d-perm]
__device__ __half g_Kh [BB*NHH*TT*HSS];     // [bh][t][d-perm]
__device__ __half g_Vth[BB*NHH*HSS*TT];     // [bh][d][t-perm]  (transposed)
__device__ __half g_Yh [BB*TT*HH];          // [b][t][h-perm]
__device__ __half g_Xh [BB*TT*HH];          // k-perm fp16 x
__device__ __half g_Wqh[HH*HH];
__device__ __half g_Wkh[HH*HH];
__device__ __half g_Wvh[HH*HH];
__device__ __half g_Woh[HH*HH];

// ---------------------------------------------------------------------------
// helpers
// ---------------------------------------------------------------------------
__device__ __forceinline__ uint32_t f22h2(float lo, float hi) {
    __half2 h = __float22half2_rn(make_float2(lo, hi));
    return *reinterpret_cast<uint32_t*>(&h);
}

__device__ __forceinline__ float ex2f(float x) {
    float r;
    asm("ex2.approx.f32 %0, %1;" : "=f"(r) : "f"(x));
    return r;
}

__device__ __forceinline__ void mma_f16(float c[4], const uint32_t a[4],
                                        const uint32_t b[2]) {
    asm volatile(
        "mma.sync.aligned.m16n8k16.row.col.f32.f16.f16.f32 "
        "{%0,%1,%2,%3}, {%4,%5,%6,%7}, {%8,%9}, {%0,%1,%2,%3};\n"
        : "+f"(c[0]), "+f"(c[1]), "+f"(c[2]), "+f"(c[3])
        : "r"(a[0]), "r"(a[1]), "r"(a[2]), "r"(a[3]),
          "r"(b[0]), "r"(b[1]));
}

#define CPA16(dst_u32, src_ptr) \
    asm volatile("cp.async.cg.shared.global [%0], [%1], 16;" \
                 :: "r"(dst_u32), "l"(src_ptr))
#define CPA_COMMIT()  asm volatile("cp.async.commit_group;")
#define CPA_WAITG(n)  asm volatile("cp.async.wait_group %0;" :: "n"(n))

// softmax in log2 domain: scale = 0.125 * log2(e); mask = -1e10 * that scale
#define SSCL   0.1803368801111832f
#define MASKV  -1.803368801e9f

// ---------------------------------------------------------------------------
// cvt: fp32 -> fp16 with per-16-element k-interleave permutation (R10).
// ---------------------------------------------------------------------------
__global__ void cvt_kernel(const float* __restrict__ x,
                           const float* __restrict__ Wq,
                           const float* __restrict__ Wk,
                           const float* __restrict__ Wv,
                           const float* __restrict__ Wo,
                           __half* __restrict__ Xh,
                           __half* __restrict__ Wqh, __half* __restrict__ Wkh,
                           __half* __restrict__ Wvh, __half* __restrict__ Woh)
{
    const int NX = (BB*TT*HH)/16;   // 262144 groups
    const int NW = (HH*HH)/16;      // 65536 per weight
    const int total = NX + 4*NW;
    for (int idx = blockIdx.x*blockDim.x + threadIdx.x; idx < total;
         idx += gridDim.x*blockDim.x) {
        const float4* s; uint4* d; int g;
        if (idx < NX) { s = (const float4*)x; d = (uint4*)Xh; g = idx; }
        else {
            int i = idx - NX, sel = i >> 16; g = i & 65535;
            s = (sel==0) ? (const float4*)Wq : (sel==1) ? (const float4*)Wk
              : (sel==2) ? (const float4*)Wv : (const float4*)Wo;
            d = (sel==0) ? (uint4*)Wqh : (sel==1) ? (uint4*)Wkh
              : (sel==2) ? (uint4*)Wvh : (uint4*)Woh;
        }
        float4 A = s[g*4+0], B = s[g*4+1], C = s[g*4+2], D = s[g*4+3];
        uint4 o0 = make_uint4(f22h2(A.x,A.y), f22h2(C.x,C.y),
                              f22h2(A.z,A.w), f22h2(C.z,C.w));
        uint4 o1 = make_uint4(f22h2(B.x,B.y), f22h2(D.x,D.y),
                              f22h2(B.z,B.w), f22h2(D.z,D.w));
        d[g*2+0] = o0;
        d[g*2+1] = o1;
    }
}

// ---------------------------------------------------------------------------
// fp16 GEMM body: block 128x128, BK=64, 256 thr, 8 warps 64x32 (R10 shape).
// smem stride 40 words/row (32 used, pad 8) -> same conflict-free pattern
// (40 = 24 mod 32). 2 stages x 2 operands x 20480 B = 81920 B dynamic.
// 16 iterations of 4 ks-steps (64 MMAs) -> half the syncs of BK=32.
// ---------------------------------------------------------------------------
struct GemmAcc { float c[4][4][4]; };

#define GSTR 40
#define GTILE (128*GSTR)

__device__ __forceinline__ void gemm_body_f16(const __half* __restrict__ A,
                                              const __half* __restrict__ W,
                                              uint32_t* dsm,
                                              int m0, int n0, GemmAcc& G)
{
    const int tid  = threadIdx.x;
    const int lane = tid & 31;
    const int w    = tid >> 5;
    const int g    = lane >> 2;
    const int t4   = lane & 3;
    const int wm   = w >> 2;
    const int wn   = w & 3;
    const uint32_t smaddr = (uint32_t)__cvta_generic_to_shared(dsm);

    #pragma unroll
    for (int im = 0; im < 4; im++)
        #pragma unroll
        for (int in = 0; in < 4; in++)
            #pragma unroll
            for (int q = 0; q < 4; q++) G.c[im][in][q] = 0.f;

    auto issue = [&](int tile, int st) {
        const int kt = tile * 64;                    // halves
        const uint32_t ab = smaddr + st*GTILE*4;
        const uint32_t bb = smaddr + (2*GTILE + st*GTILE)*4;
        #pragma unroll
        for (int l = 0; l < 4; l++) {
            int e = l*256 + tid, r = e >> 3, c = e & 7;
            CPA16(ab + (r*GSTR + c*4)*4, A + (size_t)(m0 + r)*1024 + kt + c*8);
            CPA16(bb + (r*GSTR + c*4)*4, W + (size_t)(n0 + r)*1024 + kt + c*8);
        }
        CPA_COMMIT();
    };

    issue(0, 0);

    for (int i = 0; i < 16; i++) {
        CPA_WAITG(0);
        __syncthreads();
        if (i + 1 < 16) issue(i + 1, (i + 1) & 1);

        const uint32_t* As = dsm + (i & 1)*GTILE;
        const uint32_t* Bs = dsm + 2*GTILE + (i & 1)*GTILE;
        #pragma unroll
        for (int ks = 0; ks < 4; ks++) {
            const int base = ks*8 + 2*t4;
            uint32_t af[4][4], bf[4][2];
            #pragma unroll
            for (int im = 0; im < 4; im++) {
                int r0 = wm*64 + im*16 + g;
                uint2 lo = *(const uint2*)&As[r0*GSTR + base];
                uint2 hi = *(const uint2*)&As[(r0+8)*GSTR + base];
                af[im][0] = lo.x; af[im][1] = hi.x;
                af[im][2] = lo.y; af[im][3] = hi.y;
            }
            #pragma unroll
            for (int in = 0; in < 4; in++) {
                int n = wn*32 + in*8 + g;
                uint2 y = *(const uint2*)&Bs[n*GSTR + base];
                bf[in][0] = y.x; bf[in][1] = y.y;
            }
            #pragma unroll
            for (int im = 0; im < 4; im++)
                #pragma unroll
                for (int in = 0; in < 4; in++)
                    mma_f16(G.c[im][in], af[im], bf[in]);
        }
    }
}

// ---------------------------------------------------------------------------
// Fused QKV projection. grid (8, 32, 3): z selects {Q, K, V}.
// ---------------------------------------------------------------------------
__global__ __launch_bounds__(256, 2)
void gemm_qkv(const __half* __restrict__ Xh,
              const __half* __restrict__ Wqh, const __half* __restrict__ Wkh,
              const __half* __restrict__ Wvh,
              const float* __restrict__ bq, const float* __restrict__ bk,
              const float* __restrict__ bv,
              const float* __restrict__ rope,
              __half* __restrict__ Qh, __half* __restrict__ Kh,
              __half* __restrict__ Vth)
{
    extern __shared__ uint32_t dsm[];

    const int z = blockIdx.z;
    const __half* W   = (z == 0) ? Wqh : (z == 1) ? Wkh : Wvh;
    const float* bias = (z == 0) ? bq  : (z == 1) ? bk  : bv;

    const int m0 = blockIdx.y * 128;
    const int n0 = blockIdx.x * 128;

    GemmAcc G;
    gemm_body_f16(Xh, W, dsm, m0, n0, G);

    const int lane = threadIdx.x & 31;
    const int w    = threadIdx.x >> 5;
    const int g    = lane >> 2;
    const int t4   = lane & 3;
    const int wm   = w >> 2;
    const int wn   = w & 3;

    #pragma unroll
    for (int im = 0; im < 4; im++) {
        #pragma unroll
        for (int rh = 0; rh < 2; rh++) {
            int m  = m0 + wm*64 + im*16 + g + rh*8;
            int b  = m >> 11;
            int tt = m & 2047;
            #pragma unroll
            for (int in = 0; in < 4; in++) {
                int n = n0 + wn*32 + in*8 + 2*t4;
                float v0 = G.c[im][in][rh*2 + 0] + bias[n];
                float v1 = G.c[im][in][rh*2 + 1] + bias[n+1];
                int h = n >> 6, d = n & 63;
                if (z < 2) {
                    int i0 = d >> 1;
                    float cs = rope[((size_t)tt*32 + i0)*2 + 0];
                    float sn = rope[((size_t)tt*32 + i0)*2 + 1];
                    float nv0 = cs*v0 - sn*v1;
                    float nv1 = sn*v0 + cs*v1;
                    int wd = d >> 1, blk = wd >> 3, ib = wd & 7;
                    int wp = blk*8 + ((ib < 4) ? 2*ib : 2*(ib-4) + 1);
                    uint32_t* oh = (uint32_t*)((z == 0) ? Qh : Kh);
                    oh[((size_t)(b*NHH + h)*TT + tt)*32 + wp] = f22h2(nv0, nv1);
                } else {
                    int tl = tt & 15;
                    int tlp = 2*tl - (tl & 1) - ((tl >> 3)*14);
                    size_t base = (size_t)(b*NHH + h)*64;
                    size_t tcol = (size_t)(tt & ~15) + tlp;
                    Vth[(base + d    )*TT + tcol] = __float2half_rn(v0);
                    Vth[(base + d + 1)*TT + tcol] = __float2half_rn(v1);
                }
            }
        }
    }
}

// ---------------------------------------------------------------------------
// Output projection: out[m,n] = Yh @ Woh^T (fp32 result).
// ---------------------------------------------------------------------------
__global__ __launch_bounds__(256, 2)
void gemm_out(const __half* __restrict__ Yh, const __half* __restrict__ Woh,
              float* __restrict__ out)
{
    extern __shared__ uint32_t dsm[];

    const int m0 = blockIdx.y * 128;
    const int n0 = blockIdx.x * 128;

    GemmAcc G;
    gemm_body_f16(Yh, Woh, dsm, m0, n0, G);

    const int lane = threadIdx.x & 31;
    const int w    = threadIdx.x >> 5;
    const int g    = lane >> 2;
    const int t4   = lane & 3;
    const int wm   = w >> 2;
    const int wn   = w & 3;

    #pragma unroll
    for (int im = 0; im < 4; im++) {
        #pragma unroll
        for (int rh = 0; rh < 2; rh++) {
            int m = m0 + wm*64 + im*16 + g + rh*8;
            #pragma unroll
            for (int in = 0; in < 4; in++) {
                int n = n0 + wn*32 + in*8 + 2*t4;
                *(float2*)(out + (size_t)m*1024 + n) =
                    make_float2(G.c[im][in][rh*2 + 0], G.c[im][in][rh*2 + 1]);
            }
        }
    }
}

// ---------------------------------------------------------------------------
// fp16 MMA flash attention — R10 structure (q-tile 64, 128 threads),
// softmax moved to log2 domain (ex2.approx, mask = MASKV).
// ---------------------------------------------------------------------------
#define KSTR 40
#define VSTR 40
#define ABUF (64*KSTR + 64*VSTR + 64)

__global__ __launch_bounds__(128)
void attn_mma(const __half* __restrict__ Q,
              const __half* __restrict__ K,
              const __half* __restrict__ Vt,
              const int* __restrict__ masks,
              __half* __restrict__ Y)
{
    extern __shared__ uint32_t sm[];
    __shared__ int s_any;

    const int tid  = threadIdx.x;
    const int w    = tid >> 5;
    const int lane = tid & 31;
    const int g    = lane >> 2;
    const int t4   = lane & 3;
    const int bh   = blockIdx.y;
    const int b    = bh >> 4;
    const int h    = bh & 15;
    const int qt   = gridDim.x - 1 - blockIdx.x;
    const int q0   = qt * 64;
    const __half* Qb  = Q  + (size_t)bh*TT*HSS;
    const __half* Kb  = K  + (size_t)bh*TT*HSS;
    const __half* Vtb = Vt + (size_t)bh*HSS*TT;
    const int*    mb  = masks + b*TT;
    const uint32_t smaddr = (uint32_t)__cvta_generic_to_shared(sm);

    const int qr0 = q0 + w*16 + g;
    const int qr1 = qr0 + 8;

    #pragma unroll
    for (int l = 0; l < 4; l++) {
        int e = l*128 + tid, r = e >> 3, c = e & 7;
        *(uint4*)&sm[r*KSTR + c*4] =
            *(const uint4*)(Qb + (size_t)(q0 + r)*HSS + c*8);
    }
    __syncthreads();
    uint32_t qf[4][4];
    {
        const int qrow0 = (w*16 + g)*KSTR;
        const int qrow1 = (w*16 + g + 8)*KSTR;
        #pragma unroll
        for (int ks = 0; ks < 4; ks++) {
            uint2 lo = *(const uint2*)&sm[qrow0 + ks*8 + 2*t4];
            uint2 hi = *(const uint2*)&sm[qrow1 + ks*8 + 2*t4];
            qf[ks][0] = lo.x; qf[ks][1] = hi.x;
            qf[ks][2] = lo.y; qf[ks][3] = hi.y;
        }
    }
    __syncthreads();

    auto issue = [&](int j, int s) {
        const int kbase = j*64;
        const uint32_t base = smaddr + s*ABUF*4;
        #pragma unroll
        for (int l = 0; l < 4; l++) {
            int e = l*128 + tid, r = e >> 3, c = e & 7;
            CPA16(base + (r*KSTR + c*4)*4,
                  Kb + (size_t)(kbase + r)*HSS + c*8);
            CPA16(base + (64*KSTR + r*VSTR + c*4)*4,
                  Vtb + (size_t)r*TT + kbase + c*8);
        }
        if (tid < 16)
            CPA16(base + (64*KSTR + 64*VSTR)*4 + tid*16, mb + kbase + tid*4);
        CPA_COMMIT();
    };

    float oc[8][4];
    #pragma unroll
    for (int n = 0; n < 8; n++)
        #pragma unroll
        for (int q = 0; q < 4; q++) oc[n][q] = 0.f;
    float mrun0 = -1e30f, mrun1 = -1e30f;
    float l0 = 0.f, l1 = 0.f;

    const int nkt = qt + 1;
    issue(0, 0);

    for (int j = 0; j < nkt; j++) {
        const int s = j & 1;
        __syncthreads();
        if (j + 1 < nkt) { issue(j + 1, s ^ 1); CPA_WAITG(1); }
        else             { CPA_WAITG(0); }
        __syncthreads();

        const uint32_t* Ks = sm + s*ABUF;
        const uint32_t* Vs = Ks + 64*KSTR;
        const int*      mi = (const int*)(Vs + 64*VSTR);
        const int kbase = j*64;

        float sc[8][4];
        #pragma unroll
        for (int n = 0; n < 8; n++)
            #pragma unroll
            for (int q = 0; q < 4; q++) sc[n][q] = 0.f;
        #pragma unroll
        for (int ks = 0; ks < 4; ks++) {
            #pragma unroll
            for (int n = 0; n < 8; n++) {
                uint2 y = *(const uint2*)&Ks[(n*8 + g)*KSTR + ks*8 + 2*t4];
                uint32_t bb[2] = {y.x, y.y};
                mma_f16(sc[n], qf[ks], bb);
            }
        }

        const bool diag = (j == qt);
        float mx0 = -1e30f, mx1 = -1e30f;
        #pragma unroll
        for (int n = 0; n < 8; n++) {
            bool m0i = mi[n*8 + 2*t4]     != 0;
            bool m1i = mi[n*8 + 2*t4 + 1] != 0;
            bool x00 = m0i, x01 = m1i, x10 = m0i, x11 = m1i;
            if (diag) {
                int c0 = kbase + n*8 + 2*t4;
                int c1 = c0 + 1;
                x00 |= (c0 > qr0); x01 |= (c1 > qr0);
                x10 |= (c0 > qr1); x11 |= (c1 > qr1);
            }
            float s00 = x00 ? MASKV : sc[n][0]*SSCL;
            float s01 = x01 ? MASKV : sc[n][1]*SSCL;
            float s10 = x10 ? MASKV : sc[n][2]*SSCL;
            float s11 = x11 ? MASKV : sc[n][3]*SSCL;
            sc[n][0] = s00; sc[n][1] = s01; sc[n][2] = s10; sc[n][3] = s11;
            mx0 = fmaxf(mx0, fmaxf(s00, s01));
            mx1 = fmaxf(mx1, fmaxf(s10, s11));
        }
        mx0 = fmaxf(mx0, __shfl_xor_sync(0xffffffffu, mx0, 1));
        mx0 = fmaxf(mx0, __shfl_xor_sync(0xffffffffu, mx0, 2));
        mx1 = fmaxf(mx1, __shfl_xor_sync(0xffffffffu, mx1, 1));
        mx1 = fmaxf(mx1, __shfl_xor_sync(0xffffffffu, mx1, 2));

        float mnew0 = fmaxf(mrun0, mx0);
        float mnew1 = fmaxf(mrun1, mx1);
        float corr0 = ex2f(mrun0 - mnew0);
        float corr1 = ex2f(mrun1 - mnew1);
        mrun0 = mnew0; mrun1 = mnew1;

        float ps0 = 0.f, ps1 = 0.f;
        #pragma unroll
        for (int n = 0; n < 8; n++) {
            float p00 = ex2f(sc[n][0] - mnew0);
            float p01 = ex2f(sc[n][1] - mnew0);
            float p10 = ex2f(sc[n][2] - mnew1);
            float p11 = ex2f(sc[n][3] - mnew1);
            ps0 += p00 + p01;
            ps1 += p10 + p11;
            sc[n][0] = p00; sc[n][1] = p01; sc[n][2] = p10; sc[n][3] = p11;
        }
        ps0 += __shfl_xor_sync(0xffffffffu, ps0, 1);
        ps0 += __shfl_xor_sync(0xffffffffu, ps0, 2);
        ps1 += __shfl_xor_sync(0xffffffffu, ps1, 1);
        ps1 += __shfl_xor_sync(0xffffffffu, ps1, 2);
        l0 = l0*corr0 + ps0;
        l1 = l1*corr1 + ps1;

        #pragma unroll
        for (int n = 0; n < 8; n++) {
            oc[n][0] *= corr0; oc[n][1] *= corr0;
            oc[n][2] *= corr1; oc[n][3] *= corr1;
        }

        #pragma unroll
        for (int c = 0; c < 4; c++) {
            uint32_t a[4];
            a[0] = f22h2(sc[2*c][0],   sc[2*c][1]);
            a[1] = f22h2(sc[2*c][2],   sc[2*c][3]);
            a[2] = f22h2(sc[2*c+1][0], sc[2*c+1][1]);
            a[3] = f22h2(sc[2*c+1][2], sc[2*c+1][3]);
            #pragma unroll
            for (int n = 0; n < 8; n++) {
                uint2 y = *(const uint2*)&Vs[(n*8 + g)*VSTR + c*8 + 2*t4];
                uint32_t bb[2] = {y.x, y.y};
                mma_f16(oc[n], a, bb);
            }
        }
    }

    bool dg0 = mrun0 < 0.9f*MASKV;
    bool dg1 = mrun1 < 0.9f*MASKV;
    if (tid == 0) s_any = 0;
    __syncthreads();
    if (dg0 || dg1) s_any = 1;
    __syncthreads();
    if (s_any) {
        uint32_t* Vs0 = sm + 64*KSTR;
        uint32_t one2 = f22h2(1.f, 1.f);
        uint32_t a[4];
        a[0] = dg0 ? one2 : 0u;
        a[1] = dg1 ? one2 : 0u;
        a[2] = a[0];
        a[3] = a[1];
        for (int j = nkt; j < TT/64; j++) {
            __syncthreads();
            #pragma unroll
            for (int l = 0; l < 4; l++) {
                int e = l*128 + tid, r = e >> 3, c = e & 7;
                *(uint4*)&Vs0[r*VSTR + c*4] =
                    *(const uint4*)(Vtb + (size_t)r*TT + j*64 + c*8);
            }
            __syncthreads();
            #pragma unroll
            for (int c = 0; c < 4; c++) {
                #pragma unroll
                for (int n = 0; n < 8; n++) {
                    uint2 y = *(const uint2*)&Vs0[(n*8 + g)*VSTR + c*8 + 2*t4];
                    uint32_t bb[2] = {y.x, y.y};
                    mma_f16(oc[n], a, bb);
                }
            }
        }
        float add = 64.f * (TT/64 - nkt);
        if (dg0) l0 += add;
        if (dg1) l1 += add;
    }

    // normalize + store fp16 (feature-permuted for gemm_out)
    float inv0 = 1.f / l0;
    float inv1 = 1.f / l1;
    int t0 = q0 + w*16 + g;
    uint32_t* Yw = (uint32_t*)Y;
    size_t base0 = (size_t)(b*TT + t0    )*512 + h*32;
    size_t base1 = (size_t)(b*TT + t0 + 8)*512 + h*32;
    #pragma unroll
    for (int n = 0; n < 8; n++) {
        int wp = (n >> 1)*8 + 2*t4 + (n & 1);
        Yw[base0 + wp] = f22h2(oc[n][0]*inv0, oc[n][1]*inv0);
        Yw[base1 + wp] = f22h2(oc[n][2]*inv1, oc[n][3]*inv1);
    }
}

// ---------------------------------------------------------------------------
extern "C" void kernel_launch(void* const* d_in, const int* in_sizes, int n_in,
                              void* d_out, int out_size)
{
    const float* x     = (const float*)d_in[0];
    const int*   masks = (const int*)  d_in[1];
    const float* Wq    = (const float*)d_in[2];
    const float* bq    = (const float*)d_in[3];
    const float* Wk    = (const float*)d_in[4];
    const float* bk    = (const float*)d_in[5];
    const float* Wv    = (const float*)d_in[6];
    const float* bv    = (const float*)d_in[7];
    const float* Wo    = (const float*)d_in[8];
    const float* rope  = (const float*)d_in[9];
    float* out = (float*)d_out;

    __half *Qh, *Kh, *Vth, *Yh, *Xh, *Wqh, *Wkh, *Wvh, *Woh;
    cudaGetSymbolAddress((void**)&Qh,  g_Qh);
    cudaGetSymbolAddress((void**)&Kh,  g_Kh);
    cudaGetSymbolAddress((void**)&Vth, g_Vth);
    cudaGetSymbolAddress((void**)&Yh,  g_Yh);
    cudaGetSymbolAddress((void**)&Xh,  g_Xh);
    cudaGetSymbolAddress((void**)&Wqh, g_Wqh);
    cudaGetSymbolAddress((void**)&Wkh, g_Wkh);
    cudaGetSymbolAddress((void**)&Wvh, g_Wvh);
    cudaGetSymbolAddress((void**)&Woh, g_Woh);

    const int gemm_smem = 4*GTILE*(int)sizeof(uint32_t);   // 81920 B
    const int attn_smem = 2*ABUF*(int)sizeof(uint32_t);    // 41472 B
    cudaFuncSetAttribute(gemm_qkv,
                         cudaFuncAttributeMaxDynamicSharedMemorySize, gemm_smem);
    cudaFuncSetAttribute(gemm_out,
                         cudaFuncAttributeMaxDynamicSharedMemorySize, gemm_smem);
    cudaFuncSetAttribute(attn_mma,
                         cudaFuncAttributeMaxDynamicSharedMemorySize, attn_smem);

    cvt_kernel<<<2048, 256>>>(x, Wq, Wk, Wv, Wo, Xh, Wqh, Wkh, Wvh, Woh);

    gemm_qkv<<<dim3(8, 32, 3), 256, gemm_smem>>>(Xh, Wqh, Wkh, Wvh,
                                                 bq, bk, bv, rope,
                                                 Qh, Kh, Vth);

    attn_mma<<<dim3(TT/64, BB*NHH), 128, attn_smem>>>(Qh, Kh, Vth, masks, Yh);

    gemm_out<<<dim3(8, 32), 256, gemm_smem>>>(Yh, Woh, out);
}